// round 1
// baseline (speedup 1.0000x reference)
#include <cuda_runtime.h>
#include <math.h>

// CliffordBatchNorm: x (B,H,W,C,I) = (32,64,64,64,4) fp32
// Per-channel whitening (Cholesky of 4x4 covariance) + affine.
// Folded into per-channel 4x4 affine: out = A_c * x + d_c.

#define C_CH        64
#define NSUM        14          // 4 first moments + 10 upper-tri second moments
#define R1_BLOCKS   256
#define R1_THREADS  256
#define SUBS_PER_BLK (R1_THREADS / C_CH)            // 4
#define PARTS_PER_CH (R1_BLOCKS * SUBS_PER_BLK)     // 1024
#define EPS 1e-05f

// Deterministic scratch (no atomics, no allocations)
__device__ float g_partials[C_CH * PARTS_PER_CH * NSUM];   // ~3.7 MB
__device__ float g_params[C_CH * 20];                      // A (16) + d (4) per channel

// ---------------------------------------------------------------------------
// Kernel 1: per-channel moment accumulation. Each thread owns one channel
// (tid & 63 is invariant under the grid-stride because stride % 64 == 0).
// ---------------------------------------------------------------------------
__global__ void __launch_bounds__(R1_THREADS)
stats_kernel(const float* __restrict__ x, long total_groups) {
    const int tid = threadIdx.x;
    const int c   = tid & (C_CH - 1);
    const long stride = (long)gridDim.x * blockDim.x;
    long g = (long)blockIdx.x * blockDim.x + tid;

    float s0=0.f,s1=0.f,s2=0.f,s3=0.f;
    float q00=0.f,q01=0.f,q02=0.f,q03=0.f;
    float q11=0.f,q12=0.f,q13=0.f;
    float q22=0.f,q23=0.f,q33=0.f;

    const float4* __restrict__ x4 = (const float4*)x;
    for (; g < total_groups; g += stride) {
        float4 v = __ldg(&x4[g]);
        s0 += v.x; s1 += v.y; s2 += v.z; s3 += v.w;
        q00 += v.x*v.x; q01 += v.x*v.y; q02 += v.x*v.z; q03 += v.x*v.w;
        q11 += v.y*v.y; q12 += v.y*v.z; q13 += v.y*v.w;
        q22 += v.z*v.z; q23 += v.z*v.w;
        q33 += v.w*v.w;
    }

    const int part = blockIdx.x * SUBS_PER_BLK + (tid >> 6);
    float* __restrict__ p = &g_partials[((long)c * PARTS_PER_CH + part) * NSUM];
    p[0]=s0;  p[1]=s1;  p[2]=s2;  p[3]=s3;
    p[4]=q00; p[5]=q01; p[6]=q02; p[7]=q03;
    p[8]=q11; p[9]=q12; p[10]=q13;
    p[11]=q22; p[12]=q23; p[13]=q33;
}

// ---------------------------------------------------------------------------
// Kernel 2: one block per channel. Reduce partials deterministically, then
// thread 0 does: mean/cov -> Cholesky -> L^-1 -> A = W @ L^-1, d = b - A*mu.
// ---------------------------------------------------------------------------
__global__ void __launch_bounds__(256)
solve_kernel(const float* __restrict__ weight,   // (I, I, C): [(i*4+j)*64 + c]
             const float* __restrict__ bias,     // (I, C):    [i*64 + c]
             float n_count) {
    const int c   = blockIdx.x;
    const int tid = threadIdx.x;

    __shared__ float sm[NSUM][256];

    float acc[NSUM];
    #pragma unroll
    for (int k = 0; k < NSUM; k++) acc[k] = 0.f;

    // Fixed-order accumulation: 4 partials per thread.
    for (int g = tid; g < PARTS_PER_CH; g += 256) {
        const float* __restrict__ p = &g_partials[((long)c * PARTS_PER_CH + g) * NSUM];
        #pragma unroll
        for (int k = 0; k < NSUM; k++) acc[k] += p[k];
    }
    #pragma unroll
    for (int k = 0; k < NSUM; k++) sm[k][tid] = acc[k];
    __syncthreads();

    for (int s = 128; s > 0; s >>= 1) {
        if (tid < s) {
            #pragma unroll
            for (int k = 0; k < NSUM; k++) sm[k][tid] += sm[k][tid + s];
        }
        __syncthreads();
    }

    if (tid == 0) {
        const float inv_n = 1.0f / n_count;
        float m[4];
        #pragma unroll
        for (int i = 0; i < 4; i++) m[i] = sm[i][0] * inv_n;

        // second-moment order: q00 q01 q02 q03 q11 q12 q13 q22 q23 q33 at sm[4..13]
        float cov[4][4];
        const int qidx[4][4] = { {4,5,6,7}, {5,8,9,10}, {6,9,11,12}, {7,10,12,13} };
        #pragma unroll
        for (int i = 0; i < 4; i++)
            #pragma unroll
            for (int j = 0; j < 4; j++)
                cov[i][j] = sm[qidx[i][j]][0] * inv_n - m[i]*m[j];
        #pragma unroll
        for (int i = 0; i < 4; i++) cov[i][i] += EPS;

        // Cholesky (lower)
        float L[4][4] = {};
        #pragma unroll
        for (int i = 0; i < 4; i++) {
            #pragma unroll
            for (int j = 0; j <= i; j++) {
                float sum = cov[i][j];
                #pragma unroll
                for (int k = 0; k < 4; k++)
                    if (k < j) sum -= L[i][k]*L[j][k];
                if (i == j) L[i][i] = sqrtf(sum);
                else        L[i][j] = sum / L[j][j];
            }
        }

        // Invert lower-triangular L (forward substitution)
        float Li[4][4] = {};
        #pragma unroll
        for (int j = 0; j < 4; j++) {
            Li[j][j] = 1.0f / L[j][j];
            #pragma unroll
            for (int i = 0; i < 4; i++) {
                if (i > j) {
                    float sum = 0.f;
                    #pragma unroll
                    for (int k = 0; k < 4; k++)
                        if (k >= j && k < i) sum += L[i][k]*Li[k][j];
                    Li[i][j] = -sum / L[i][i];
                }
            }
        }

        // A = W_c @ Li ; d = b_c - A @ m
        float A[4][4], d[4];
        #pragma unroll
        for (int i = 0; i < 4; i++) {
            #pragma unroll
            for (int j = 0; j < 4; j++) {
                float sum = 0.f;
                #pragma unroll
                for (int k = 0; k < 4; k++)
                    sum += weight[(i*4 + k)*C_CH + c] * Li[k][j];
                A[i][j] = sum;
            }
        }
        #pragma unroll
        for (int i = 0; i < 4; i++) {
            float s = bias[i*C_CH + c];
            #pragma unroll
            for (int j = 0; j < 4; j++) s -= A[i][j] * m[j];
            d[i] = s;
        }

        float* __restrict__ P = &g_params[c * 20];
        #pragma unroll
        for (int i = 0; i < 4; i++)
            #pragma unroll
            for (int j = 0; j < 4; j++)
                P[i*4 + j] = A[i][j];
        #pragma unroll
        for (int i = 0; i < 4; i++) P[16 + i] = d[i];
    }
}

// ---------------------------------------------------------------------------
// Kernel 3: out = A_c * x + d_c, streaming float4 -> float4.
// ---------------------------------------------------------------------------
__global__ void __launch_bounds__(256)
apply_kernel(const float* __restrict__ x, float* __restrict__ out,
             long total_groups) {
    const int tid = threadIdx.x;
    const int c   = tid & (C_CH - 1);
    const float* __restrict__ P = &g_params[c * 20];

    const float A00=P[0],  A01=P[1],  A02=P[2],  A03=P[3];
    const float A10=P[4],  A11=P[5],  A12=P[6],  A13=P[7];
    const float A20=P[8],  A21=P[9],  A22=P[10], A23=P[11];
    const float A30=P[12], A31=P[13], A32=P[14], A33=P[15];
    const float d0=P[16], d1=P[17], d2=P[18], d3=P[19];

    const long stride = (long)gridDim.x * blockDim.x;
    const float4* __restrict__ x4 = (const float4*)x;
    float4* __restrict__ o4 = (float4*)out;

    for (long g = (long)blockIdx.x * blockDim.x + tid; g < total_groups; g += stride) {
        float4 v = __ldg(&x4[g]);
        float4 o;
        o.x = fmaf(A00, v.x, fmaf(A01, v.y, fmaf(A02, v.z, fmaf(A03, v.w, d0))));
        o.y = fmaf(A10, v.x, fmaf(A11, v.y, fmaf(A12, v.z, fmaf(A13, v.w, d1))));
        o.z = fmaf(A20, v.x, fmaf(A21, v.y, fmaf(A22, v.z, fmaf(A23, v.w, d2))));
        o.w = fmaf(A30, v.x, fmaf(A31, v.y, fmaf(A32, v.z, fmaf(A33, v.w, d3))));
        o4[g] = o;
    }
}

// ---------------------------------------------------------------------------
extern "C" void kernel_launch(void* const* d_in, const int* in_sizes, int n_in,
                              void* d_out, int out_size) {
    const float* x      = (const float*)d_in[0];   // (B,H,W,C,I) fp32
    const float* weight = (const float*)d_in[1];   // (I,I,C)
    const float* bias   = (const float*)d_in[2];   // (I,C)
    float* out = (float*)d_out;

    const long total_elems  = (long)in_sizes[0];
    const long total_groups = total_elems / 4;            // (B*H*W*C) float4 vectors
    const float n_count     = (float)(total_groups / C_CH); // B*H*W samples per channel

    stats_kernel<<<R1_BLOCKS, R1_THREADS>>>(x, total_groups);
    solve_kernel<<<C_CH, 256>>>(weight, bias, n_count);
    apply_kernel<<<2048, 256>>>(x, out, total_groups);
}

// round 3
// speedup vs baseline: 1.1049x; 1.1049x over previous
#include <cuda_runtime.h>
#include <math.h>

// CliffordBatchNorm: x (B,H,W,C,I) = (32,64,64,64,4) fp32
// Per-channel whitening (Cholesky of 4x4 covariance) + affine,
// folded into per-channel 4x4 affine: out = A_c * x + d_c.

#define C_CH        64
#define NSUM        14          // 4 first moments + 10 upper-tri second moments
#define R1_BLOCKS   1024
#define R1_THREADS  256
#define PARTS_PER_CH R1_BLOCKS                      // one partial per block per channel
#define AP_BLOCKS   2048
#define EPS 1e-05f

// Deterministic scratch (no atomics, no allocations)
__device__ float g_partials[C_CH * PARTS_PER_CH * NSUM];   // ~3.7 MB
__device__ float g_params[C_CH * 20];                      // A (16) + d (4) per channel

// ---------------------------------------------------------------------------
// Kernel 1: per-channel moment accumulation. Each thread owns one channel
// (tid & 63 is invariant under the grid-stride because stride % 64 == 0).
// 4-way unrolled independent loads for MLP; in-block reduction of the 4
// per-channel sub-accumulators so partial count stays at 1 per block.
// ---------------------------------------------------------------------------
__global__ void __launch_bounds__(R1_THREADS)
stats_kernel(const float* __restrict__ x, long total_groups) {
    const int tid = threadIdx.x;
    const int c   = tid & (C_CH - 1);
    const int sub = tid >> 6;                      // 0..3
    const long stride = (long)gridDim.x * blockDim.x;

    float acc[NSUM];
    #pragma unroll
    for (int k = 0; k < NSUM; k++) acc[k] = 0.f;

    const float4* __restrict__ x4 = (const float4*)x;
    long g = (long)blockIdx.x * blockDim.x + tid;

    // main loop: 4 independent coalesced float4 loads in flight
    for (; g + 3*stride < total_groups; g += 4*stride) {
        float4 v0 = __ldcs(&x4[g]);
        float4 v1 = __ldcs(&x4[g +   stride]);
        float4 v2 = __ldcs(&x4[g + 2*stride]);
        float4 v3 = __ldcs(&x4[g + 3*stride]);
        #pragma unroll
        for (int u = 0; u < 4; u++) {
            float4 v = (u==0) ? v0 : (u==1) ? v1 : (u==2) ? v2 : v3;
            acc[0] += v.x; acc[1] += v.y; acc[2] += v.z; acc[3] += v.w;
            acc[4] += v.x*v.x; acc[5] += v.x*v.y; acc[6]  += v.x*v.z; acc[7]  += v.x*v.w;
            acc[8] += v.y*v.y; acc[9] += v.y*v.z; acc[10] += v.y*v.w;
            acc[11] += v.z*v.z; acc[12] += v.z*v.w;
            acc[13] += v.w*v.w;
        }
    }
    for (; g < total_groups; g += stride) {
        float4 v = __ldcs(&x4[g]);
        acc[0] += v.x; acc[1] += v.y; acc[2] += v.z; acc[3] += v.w;
        acc[4] += v.x*v.x; acc[5] += v.x*v.y; acc[6]  += v.x*v.z; acc[7]  += v.x*v.w;
        acc[8] += v.y*v.y; acc[9] += v.y*v.z; acc[10] += v.y*v.w;
        acc[11] += v.z*v.z; acc[12] += v.z*v.w;
        acc[13] += v.w*v.w;
    }

    // In-block reduce: 4 sub-accumulators per channel -> 1 partial per block.
    __shared__ float sm[4][C_CH][NSUM];
    #pragma unroll
    for (int k = 0; k < NSUM; k++) sm[sub][c][k] = acc[k];
    __syncthreads();

    if (tid < C_CH) {
        float out[NSUM];
        #pragma unroll
        for (int k = 0; k < NSUM; k++)
            out[k] = sm[0][tid][k] + sm[1][tid][k] + sm[2][tid][k] + sm[3][tid][k];
        float* __restrict__ p = &g_partials[((long)tid * PARTS_PER_CH + blockIdx.x) * NSUM];
        #pragma unroll
        for (int k = 0; k < NSUM; k++) p[k] = out[k];
    }
}

// ---------------------------------------------------------------------------
// Kernel 2: one block per channel. Reduce partials deterministically, then
// thread 0 does: mean/cov -> Cholesky -> L^-1 -> A = W @ L^-1, d = b - A*mu.
// ---------------------------------------------------------------------------
__global__ void __launch_bounds__(256)
solve_kernel(const float* __restrict__ weight,   // (I, I, C): [(i*4+j)*64 + c]
             const float* __restrict__ bias,     // (I, C):    [i*64 + c]
             float n_count) {
    const int c   = blockIdx.x;
    const int tid = threadIdx.x;

    __shared__ float sm[NSUM][256];

    float acc[NSUM];
    #pragma unroll
    for (int k = 0; k < NSUM; k++) acc[k] = 0.f;

    // Fixed-order accumulation: 4 partials per thread.
    for (int g = tid; g < PARTS_PER_CH; g += 256) {
        const float* __restrict__ p = &g_partials[((long)c * PARTS_PER_CH + g) * NSUM];
        #pragma unroll
        for (int k = 0; k < NSUM; k++) acc[k] += p[k];
    }
    #pragma unroll
    for (int k = 0; k < NSUM; k++) sm[k][tid] = acc[k];
    __syncthreads();

    for (int s = 128; s > 0; s >>= 1) {
        if (tid < s) {
            #pragma unroll
            for (int k = 0; k < NSUM; k++) sm[k][tid] += sm[k][tid + s];
        }
        __syncthreads();
    }

    if (tid == 0) {
        const float inv_n = 1.0f / n_count;
        float m[4];
        #pragma unroll
        for (int i = 0; i < 4; i++) m[i] = sm[i][0] * inv_n;

        // second-moment order: q00 q01 q02 q03 q11 q12 q13 q22 q23 q33 at sm[4..13]
        float cov[4][4];
        const int qidx[4][4] = { {4,5,6,7}, {5,8,9,10}, {6,9,11,12}, {7,10,12,13} };
        #pragma unroll
        for (int i = 0; i < 4; i++)
            #pragma unroll
            for (int j = 0; j < 4; j++)
                cov[i][j] = sm[qidx[i][j]][0] * inv_n - m[i]*m[j];
        #pragma unroll
        for (int i = 0; i < 4; i++) cov[i][i] += EPS;

        // Cholesky (lower)
        float L[4][4] = {};
        #pragma unroll
        for (int i = 0; i < 4; i++) {
            #pragma unroll
            for (int j = 0; j <= i; j++) {
                float sum = cov[i][j];
                #pragma unroll
                for (int k = 0; k < 4; k++)
                    if (k < j) sum -= L[i][k]*L[j][k];
                if (i == j) L[i][i] = sqrtf(sum);
                else        L[i][j] = sum / L[j][j];
            }
        }

        // Invert lower-triangular L (forward substitution)
        float Li[4][4] = {};
        #pragma unroll
        for (int j = 0; j < 4; j++) {
            Li[j][j] = 1.0f / L[j][j];
            #pragma unroll
            for (int i = 0; i < 4; i++) {
                if (i > j) {
                    float sum = 0.f;
                    #pragma unroll
                    for (int k = 0; k < 4; k++)
                        if (k >= j && k < i) sum += L[i][k]*Li[k][j];
                    Li[i][j] = -sum / L[i][i];
                }
            }
        }

        // A = W_c @ Li ; d = b_c - A @ m
        float A[4][4], d[4];
        #pragma unroll
        for (int i = 0; i < 4; i++) {
            #pragma unroll
            for (int j = 0; j < 4; j++) {
                float sum = 0.f;
                #pragma unroll
                for (int k = 0; k < 4; k++)
                    sum += weight[(i*4 + k)*C_CH + c] * Li[k][j];
                A[i][j] = sum;
            }
        }
        #pragma unroll
        for (int i = 0; i < 4; i++) {
            float s = bias[i*C_CH + c];
            #pragma unroll
            for (int j = 0; j < 4; j++) s -= A[i][j] * m[j];
            d[i] = s;
        }

        float* __restrict__ P = &g_params[c * 20];
        #pragma unroll
        for (int i = 0; i < 4; i++)
            #pragma unroll
            for (int j = 0; j < 4; j++)
                P[i*4 + j] = A[i][j];
        #pragma unroll
        for (int i = 0; i < 4; i++) P[16 + i] = d[i];
    }
}

// ---------------------------------------------------------------------------
// Kernel 3: out = A_c * x + d_c, streaming float4 -> float4.
// 4-way unrolled: 4 loads in flight, then compute+store; streaming cache
// hints keep single-use data out of L2.
// ---------------------------------------------------------------------------
__device__ __forceinline__ float4 affine4(const float* __restrict__ P, float4 v) {
    float4 o;
    o.x = fmaf(P[0],  v.x, fmaf(P[1],  v.y, fmaf(P[2],  v.z, fmaf(P[3],  v.w, P[16]))));
    o.y = fmaf(P[4],  v.x, fmaf(P[5],  v.y, fmaf(P[6],  v.z, fmaf(P[7],  v.w, P[17]))));
    o.z = fmaf(P[8],  v.x, fmaf(P[9],  v.y, fmaf(P[10], v.z, fmaf(P[11], v.w, P[18]))));
    o.w = fmaf(P[12], v.x, fmaf(P[13], v.y, fmaf(P[14], v.z, fmaf(P[15], v.w, P[19]))));
    return o;
}

__global__ void __launch_bounds__(256)
apply_kernel(const float* __restrict__ x, float* __restrict__ out,
             long total_groups) {
    const int tid = threadIdx.x;
    const int c   = tid & (C_CH - 1);

    // Load the 20 per-channel params into registers once.
    float P[20];
    #pragma unroll
    for (int k = 0; k < 20; k++) P[k] = g_params[c * 20 + k];

    const long stride = (long)gridDim.x * blockDim.x;
    const float4* __restrict__ x4 = (const float4*)x;
    float4* __restrict__ o4 = (float4*)out;

    long g = (long)blockIdx.x * blockDim.x + tid;
    for (; g + 3*stride < total_groups; g += 4*stride) {
        float4 v0 = __ldcs(&x4[g]);
        float4 v1 = __ldcs(&x4[g +   stride]);
        float4 v2 = __ldcs(&x4[g + 2*stride]);
        float4 v3 = __ldcs(&x4[g + 3*stride]);
        __stcs(&o4[g],            affine4(P, v0));
        __stcs(&o4[g +   stride], affine4(P, v1));
        __stcs(&o4[g + 2*stride], affine4(P, v2));
        __stcs(&o4[g + 3*stride], affine4(P, v3));
    }
    for (; g < total_groups; g += stride) {
        float4 v = __ldcs(&x4[g]);
        __stcs(&o4[g], affine4(P, v));
    }
}

// ---------------------------------------------------------------------------
extern "C" void kernel_launch(void* const* d_in, const int* in_sizes, int n_in,
                              void* d_out, int out_size) {
    const float* x      = (const float*)d_in[0];   // (B,H,W,C,I) fp32
    const float* weight = (const float*)d_in[1];   // (I,I,C)
    const float* bias   = (const float*)d_in[2];   // (I,C)
    float* out = (float*)d_out;

    const long total_elems  = (long)in_sizes[0];
    const long total_groups = total_elems / 4;              // (B*H*W*C) float4 vectors
    const float n_count     = (float)(total_groups / C_CH); // B*H*W samples per channel

    stats_kernel<<<R1_BLOCKS, R1_THREADS>>>(x, total_groups);
    solve_kernel<<<C_CH, 256>>>(weight, bias, n_count);
    apply_kernel<<<AP_BLOCKS, 256>>>(x, out, total_groups);
}

// round 5
// speedup vs baseline: 1.1279x; 1.0208x over previous
#include <cuda_runtime.h>
#include <math.h>

// CliffordBatchNorm: x (B,H,W,C,I) = (32,64,64,64,4) fp32
// Per-channel whitening (Cholesky of 4x4 covariance) + affine,
// folded into per-channel 4x4 affine: out = A_c * x + d_c.
//
// R4: stats uses caching loads (x tail stays in 126MB L2); apply traverses
// in REVERSE so it consumes the L2-hot tail first. Grids = 888 = 148*6
// (exactly one wave at 6 blocks/SM).

#define C_CH        64
#define NSUM        14          // 4 first moments + 10 upper-tri second moments
#define R1_BLOCKS   888
#define R1_THREADS  256
#define PARTS_PER_CH R1_BLOCKS                      // one partial per block per channel
#define AP_BLOCKS   888
#define EPS 1e-05f

// Deterministic scratch (no atomics, no allocations)
__device__ float g_partials[C_CH * PARTS_PER_CH * NSUM];
__device__ float g_params[C_CH * 20];                      // A (16) + d (4) per channel

// ---------------------------------------------------------------------------
// Kernel 1: per-channel moment accumulation. Each thread owns one channel
// (tid & 63 invariant: stride % 64 == 0). Default caching loads so the tail
// of x is L2-resident when apply starts.
// ---------------------------------------------------------------------------
__global__ void __launch_bounds__(R1_THREADS)
stats_kernel(const float* __restrict__ x, long total_groups) {
    const int tid = threadIdx.x;
    const int c   = tid & (C_CH - 1);
    const int sub = tid >> 6;                      // 0..3
    const long stride = (long)gridDim.x * blockDim.x;

    float acc[NSUM];
    #pragma unroll
    for (int k = 0; k < NSUM; k++) acc[k] = 0.f;

    const float4* __restrict__ x4 = (const float4*)x;
    long g = (long)blockIdx.x * blockDim.x + tid;

    // main loop: 4 independent coalesced float4 loads in flight
    for (; g + 3*stride < total_groups; g += 4*stride) {
        float4 v0 = x4[g];
        float4 v1 = x4[g +   stride];
        float4 v2 = x4[g + 2*stride];
        float4 v3 = x4[g + 3*stride];
        #pragma unroll
        for (int u = 0; u < 4; u++) {
            float4 v = (u==0) ? v0 : (u==1) ? v1 : (u==2) ? v2 : v3;
            acc[0] += v.x; acc[1] += v.y; acc[2] += v.z; acc[3] += v.w;
            acc[4] += v.x*v.x; acc[5] += v.x*v.y; acc[6]  += v.x*v.z; acc[7]  += v.x*v.w;
            acc[8] += v.y*v.y; acc[9] += v.y*v.z; acc[10] += v.y*v.w;
            acc[11] += v.z*v.z; acc[12] += v.z*v.w;
            acc[13] += v.w*v.w;
        }
    }
    for (; g < total_groups; g += stride) {
        float4 v = x4[g];
        acc[0] += v.x; acc[1] += v.y; acc[2] += v.z; acc[3] += v.w;
        acc[4] += v.x*v.x; acc[5] += v.x*v.y; acc[6]  += v.x*v.z; acc[7]  += v.x*v.w;
        acc[8] += v.y*v.y; acc[9] += v.y*v.z; acc[10] += v.y*v.w;
        acc[11] += v.z*v.z; acc[12] += v.z*v.w;
        acc[13] += v.w*v.w;
    }

    // In-block reduce: 4 sub-accumulators per channel -> 1 partial per block.
    __shared__ float sm[4][C_CH][NSUM];
    #pragma unroll
    for (int k = 0; k < NSUM; k++) sm[sub][c][k] = acc[k];
    __syncthreads();

    if (tid < C_CH) {
        float out[NSUM];
        #pragma unroll
        for (int k = 0; k < NSUM; k++)
            out[k] = sm[0][tid][k] + sm[1][tid][k] + sm[2][tid][k] + sm[3][tid][k];
        float* __restrict__ p = &g_partials[((long)tid * PARTS_PER_CH + blockIdx.x) * NSUM];
        #pragma unroll
        for (int k = 0; k < NSUM; k++) p[k] = out[k];
    }
}

// ---------------------------------------------------------------------------
// Kernel 2: one block per channel. Deterministic reduce, then thread 0 does
// mean/cov -> Cholesky -> L^-1 -> A = W @ L^-1, d = b - A*mu.
// ---------------------------------------------------------------------------
__global__ void __launch_bounds__(256)
solve_kernel(const float* __restrict__ weight,   // (I, I, C): [(i*4+j)*64 + c]
             const float* __restrict__ bias,     // (I, C):    [i*64 + c]
             float n_count) {
    const int c   = blockIdx.x;
    const int tid = threadIdx.x;

    __shared__ float sm[NSUM][256];

    float acc[NSUM];
    #pragma unroll
    for (int k = 0; k < NSUM; k++) acc[k] = 0.f;

    for (int g = tid; g < PARTS_PER_CH; g += 256) {
        const float* __restrict__ p = &g_partials[((long)c * PARTS_PER_CH + g) * NSUM];
        #pragma unroll
        for (int k = 0; k < NSUM; k++) acc[k] += p[k];
    }
    #pragma unroll
    for (int k = 0; k < NSUM; k++) sm[k][tid] = acc[k];
    __syncthreads();

    for (int s = 128; s > 0; s >>= 1) {
        if (tid < s) {
            #pragma unroll
            for (int k = 0; k < NSUM; k++) sm[k][tid] += sm[k][tid + s];
        }
        __syncthreads();
    }

    if (tid == 0) {
        const float inv_n = 1.0f / n_count;
        float m[4];
        #pragma unroll
        for (int i = 0; i < 4; i++) m[i] = sm[i][0] * inv_n;

        float cov[4][4];
        const int qidx[4][4] = { {4,5,6,7}, {5,8,9,10}, {6,9,11,12}, {7,10,12,13} };
        #pragma unroll
        for (int i = 0; i < 4; i++)
            #pragma unroll
            for (int j = 0; j < 4; j++)
                cov[i][j] = sm[qidx[i][j]][0] * inv_n - m[i]*m[j];
        #pragma unroll
        for (int i = 0; i < 4; i++) cov[i][i] += EPS;

        // Cholesky (lower)
        float L[4][4] = {};
        #pragma unroll
        for (int i = 0; i < 4; i++) {
            #pragma unroll
            for (int j = 0; j <= i; j++) {
                float sum = cov[i][j];
                #pragma unroll
                for (int k = 0; k < 4; k++)
                    if (k < j) sum -= L[i][k]*L[j][k];
                if (i == j) L[i][i] = sqrtf(sum);
                else        L[i][j] = sum / L[j][j];
            }
        }

        // Invert lower-triangular L
        float Li[4][4] = {};
        #pragma unroll
        for (int j = 0; j < 4; j++) {
            Li[j][j] = 1.0f / L[j][j];
            #pragma unroll
            for (int i = 0; i < 4; i++) {
                if (i > j) {
                    float sum = 0.f;
                    #pragma unroll
                    for (int k = 0; k < 4; k++)
                        if (k >= j && k < i) sum += L[i][k]*Li[k][j];
                    Li[i][j] = -sum / L[i][i];
                }
            }
        }

        // A = W_c @ Li ; d = b_c - A @ m
        float A[4][4], d[4];
        #pragma unroll
        for (int i = 0; i < 4; i++) {
            #pragma unroll
            for (int j = 0; j < 4; j++) {
                float sum = 0.f;
                #pragma unroll
                for (int k = 0; k < 4; k++)
                    sum += weight[(i*4 + k)*C_CH + c] * Li[k][j];
                A[i][j] = sum;
            }
        }
        #pragma unroll
        for (int i = 0; i < 4; i++) {
            float s = bias[i*C_CH + c];
            #pragma unroll
            for (int j = 0; j < 4; j++) s -= A[i][j] * m[j];
            d[i] = s;
        }

        float* __restrict__ P = &g_params[c * 20];
        #pragma unroll
        for (int i = 0; i < 4; i++)
            #pragma unroll
            for (int j = 0; j < 4; j++)
                P[i*4 + j] = A[i][j];
        #pragma unroll
        for (int i = 0; i < 4; i++) P[16 + i] = d[i];
    }
}

// ---------------------------------------------------------------------------
// Kernel 3: out = A_c * x + d_c. REVERSE traversal: consume the L2-hot tail
// of x (left there by stats) first. x loads default-cached; out stores
// streaming so they don't evict x.
// ---------------------------------------------------------------------------
__device__ __forceinline__ float4 affine4(const float* __restrict__ P, float4 v) {
    float4 o;
    o.x = fmaf(P[0],  v.x, fmaf(P[1],  v.y, fmaf(P[2],  v.z, fmaf(P[3],  v.w, P[16]))));
    o.y = fmaf(P[4],  v.x, fmaf(P[5],  v.y, fmaf(P[6],  v.z, fmaf(P[7],  v.w, P[17]))));
    o.z = fmaf(P[8],  v.x, fmaf(P[9],  v.y, fmaf(P[10], v.z, fmaf(P[11], v.w, P[18]))));
    o.w = fmaf(P[12], v.x, fmaf(P[13], v.y, fmaf(P[14], v.z, fmaf(P[15], v.w, P[19]))));
    return o;
}

__global__ void __launch_bounds__(256)
apply_kernel(const float* __restrict__ x, float* __restrict__ out,
             long total_groups) {
    const int tid = threadIdx.x;
    const int c   = tid & (C_CH - 1);

    float P[20];
    #pragma unroll
    for (int k = 0; k < 20; k++) P[k] = g_params[c * 20 + k];

    const long stride = (long)gridDim.x * blockDim.x;
    const float4* __restrict__ x4 = (const float4*)x;
    float4* __restrict__ o4 = (float4*)out;

    // Reversed block order + descending grid-stride: highest addresses first.
    const long g0 = (long)(gridDim.x - 1 - blockIdx.x) * blockDim.x + tid;
    long k = (g0 < total_groups) ? (total_groups - 1 - g0) / stride : -1;

    for (; k >= 3; k -= 4) {
        const long ga = g0 + k*stride;
        const long gb = ga - stride;
        const long gc = gb - stride;
        const long gd = gc - stride;
        float4 va = x4[ga];
        float4 vb = x4[gb];
        float4 vc = x4[gc];
        float4 vd = x4[gd];
        __stcs(&o4[ga], affine4(P, va));
        __stcs(&o4[gb], affine4(P, vb));
        __stcs(&o4[gc], affine4(P, vc));
        __stcs(&o4[gd], affine4(P, vd));
    }
    for (; k >= 0; k--) {
        const long g = g0 + k*stride;
        float4 v = x4[g];
        __stcs(&o4[g], affine4(P, v));
    }
}

// ---------------------------------------------------------------------------
extern "C" void kernel_launch(void* const* d_in, const int* in_sizes, int n_in,
                              void* d_out, int out_size) {
    const float* x      = (const float*)d_in[0];   // (B,H,W,C,I) fp32
    const float* weight = (const float*)d_in[1];   // (I,I,C)
    const float* bias   = (const float*)d_in[2];   // (I,C)
    float* out = (float*)d_out;

    const long total_elems  = (long)in_sizes[0];
    const long total_groups = total_elems / 4;              // (B*H*W*C) float4 vectors
    const float n_count     = (float)(total_groups / C_CH); // B*H*W samples per channel

    stats_kernel<<<R1_BLOCKS, R1_THREADS>>>(x, total_groups);
    solve_kernel<<<C_CH, 256>>>(weight, bias, n_count);
    apply_kernel<<<AP_BLOCKS, 256>>>(x, out, total_groups);
}

// round 7
// speedup vs baseline: 1.2191x; 1.0808x over previous
#include <cuda_runtime.h>
#include <math.h>

// CliffordBatchNorm, fused persistent kernel (sm_103a).
// x (B,H,W,C,I) = (32,64,64,64,4) fp32. Per-channel 4x4 whitening + affine
// folded to out = A_c * x + d_c.
//
// Phase 1: grid-stride ascending moment accumulation (per-thread channel).
// Phase 2: blocks 0..63 reduce partials + Cholesky solve -> g_params.
// Phase 3: apply, DESCENDING traversal so the L2-hot tail of x (just read
//          by phase 1) is consumed first. Single kernel => no launch gap,
//          maximal L2 reuse window. Grid barrier is a sense-reversal spin;
//          grid = 148 SM x 4 blocks, co-residency guaranteed by
//          __launch_bounds__(256, 4).

#define C_CH      64
#define NSUM      14
#define NBLOCKS   592          // 148 * 4
#define NTHREADS  256
#define EPS       1e-05f

__device__ float g_partials[C_CH * NBLOCKS * NSUM];   // ~2.1 MB, L2-resident
__device__ float g_params[C_CH * 20];                 // A (16) + d (4) per channel
__device__ unsigned int g_count;                      // barrier arrive counter
__device__ volatile unsigned int g_gen;               // barrier generation

__device__ __forceinline__ void grid_barrier() {
    __syncthreads();
    if (threadIdx.x == 0) {
        __threadfence();                               // release prior writes
        unsigned int gen = g_gen;
        if (atomicAdd(&g_count, 1u) == NBLOCKS - 1) {
            g_count = 0;
            __threadfence();
            g_gen = gen + 1;                           // release
        } else {
            while (g_gen == gen) { }                   // volatile spin
        }
        __threadfence();                               // acquire
    }
    __syncthreads();
}

__device__ __forceinline__ float4 affine4(const float* __restrict__ P, float4 v) {
    float4 o;
    o.x = fmaf(P[0],  v.x, fmaf(P[1],  v.y, fmaf(P[2],  v.z, fmaf(P[3],  v.w, P[16]))));
    o.y = fmaf(P[4],  v.x, fmaf(P[5],  v.y, fmaf(P[6],  v.z, fmaf(P[7],  v.w, P[17]))));
    o.z = fmaf(P[8],  v.x, fmaf(P[9],  v.y, fmaf(P[10], v.z, fmaf(P[11], v.w, P[18]))));
    o.w = fmaf(P[12], v.x, fmaf(P[13], v.y, fmaf(P[14], v.z, fmaf(P[15], v.w, P[19]))));
    return o;
}

__global__ void __launch_bounds__(NTHREADS, 4)
fused_kernel(const float* __restrict__ x,
             const float* __restrict__ weight,   // (I,I,C): [(i*4+j)*64 + c]
             const float* __restrict__ bias,     // (I,C):   [i*64 + c]
             float* __restrict__ out,
             long total_groups, float n_count) {
    const int tid = threadIdx.x;
    const int c   = tid & (C_CH - 1);
    const int sub = tid >> 6;                        // 0..3
    const long stride = (long)NBLOCKS * NTHREADS;    // multiple of 64

    __shared__ float sm1[4][C_CH][NSUM];             // phase-1 in-block reduce
    __shared__ float sm2[NSUM][NTHREADS];            // phase-2 reduce

    // ---------------- Phase 1: moments (ascending grid-stride) -------------
    {
        float acc[NSUM];
        #pragma unroll
        for (int k = 0; k < NSUM; k++) acc[k] = 0.f;

        const float4* __restrict__ x4 = (const float4*)x;
        long g = (long)blockIdx.x * NTHREADS + tid;

        for (; g + 3*stride < total_groups; g += 4*stride) {
            float4 v0 = x4[g];
            float4 v1 = x4[g +   stride];
            float4 v2 = x4[g + 2*stride];
            float4 v3 = x4[g + 3*stride];
            #pragma unroll
            for (int u = 0; u < 4; u++) {
                float4 v = (u==0) ? v0 : (u==1) ? v1 : (u==2) ? v2 : v3;
                acc[0] += v.x; acc[1] += v.y; acc[2] += v.z; acc[3] += v.w;
                acc[4] += v.x*v.x; acc[5] += v.x*v.y; acc[6]  += v.x*v.z; acc[7]  += v.x*v.w;
                acc[8] += v.y*v.y; acc[9] += v.y*v.z; acc[10] += v.y*v.w;
                acc[11] += v.z*v.z; acc[12] += v.z*v.w;
                acc[13] += v.w*v.w;
            }
        }
        for (; g < total_groups; g += stride) {
            float4 v = x4[g];
            acc[0] += v.x; acc[1] += v.y; acc[2] += v.z; acc[3] += v.w;
            acc[4] += v.x*v.x; acc[5] += v.x*v.y; acc[6]  += v.x*v.z; acc[7]  += v.x*v.w;
            acc[8] += v.y*v.y; acc[9] += v.y*v.z; acc[10] += v.y*v.w;
            acc[11] += v.z*v.z; acc[12] += v.z*v.w;
            acc[13] += v.w*v.w;
        }

        #pragma unroll
        for (int k = 0; k < NSUM; k++) sm1[sub][c][k] = acc[k];
        __syncthreads();

        if (tid < C_CH) {
            float o[NSUM];
            #pragma unroll
            for (int k = 0; k < NSUM; k++)
                o[k] = sm1[0][tid][k] + sm1[1][tid][k] + sm1[2][tid][k] + sm1[3][tid][k];
            float* __restrict__ p = &g_partials[((long)tid * NBLOCKS + blockIdx.x) * NSUM];
            #pragma unroll
            for (int k = 0; k < NSUM; k++) p[k] = o[k];
        }
    }

    grid_barrier();

    // ---------------- Phase 2: reduce + solve (blocks 0..63) ---------------
    if (blockIdx.x < C_CH) {
        const int ch = blockIdx.x;

        float acc[NSUM];
        #pragma unroll
        for (int k = 0; k < NSUM; k++) acc[k] = 0.f;

        for (int g = tid; g < NBLOCKS; g += NTHREADS) {
            const float* __restrict__ p = &g_partials[((long)ch * NBLOCKS + g) * NSUM];
            #pragma unroll
            for (int k = 0; k < NSUM; k++) acc[k] += p[k];
        }
        #pragma unroll
        for (int k = 0; k < NSUM; k++) sm2[k][tid] = acc[k];
        __syncthreads();

        for (int s = 128; s > 0; s >>= 1) {
            if (tid < s) {
                #pragma unroll
                for (int k = 0; k < NSUM; k++) sm2[k][tid] += sm2[k][tid + s];
            }
            __syncthreads();
        }

        if (tid == 0) {
            const float inv_n = 1.0f / n_count;
            float m[4];
            #pragma unroll
            for (int i = 0; i < 4; i++) m[i] = sm2[i][0] * inv_n;

            float cov[4][4];
            const int qidx[4][4] = { {4,5,6,7}, {5,8,9,10}, {6,9,11,12}, {7,10,12,13} };
            #pragma unroll
            for (int i = 0; i < 4; i++)
                #pragma unroll
                for (int j = 0; j < 4; j++)
                    cov[i][j] = sm2[qidx[i][j]][0] * inv_n - m[i]*m[j];
            #pragma unroll
            for (int i = 0; i < 4; i++) cov[i][i] += EPS;

            // Cholesky (lower)
            float L[4][4] = {};
            #pragma unroll
            for (int i = 0; i < 4; i++) {
                #pragma unroll
                for (int j = 0; j <= i; j++) {
                    float sum = cov[i][j];
                    #pragma unroll
                    for (int k = 0; k < 4; k++)
                        if (k < j) sum -= L[i][k]*L[j][k];
                    if (i == j) L[i][i] = sqrtf(sum);
                    else        L[i][j] = sum / L[j][j];
                }
            }

            // Invert lower-triangular L
            float Li[4][4] = {};
            #pragma unroll
            for (int j = 0; j < 4; j++) {
                Li[j][j] = 1.0f / L[j][j];
                #pragma unroll
                for (int i = 0; i < 4; i++) {
                    if (i > j) {
                        float sum = 0.f;
                        #pragma unroll
                        for (int k = 0; k < 4; k++)
                            if (k >= j && k < i) sum += L[i][k]*Li[k][j];
                        Li[i][j] = -sum / L[i][i];
                    }
                }
            }

            // A = W_c @ Li ; d = b_c - A @ m
            float A[4][4], d[4];
            #pragma unroll
            for (int i = 0; i < 4; i++) {
                #pragma unroll
                for (int j = 0; j < 4; j++) {
                    float sum = 0.f;
                    #pragma unroll
                    for (int k = 0; k < 4; k++)
                        sum += weight[(i*4 + k)*C_CH + ch] * Li[k][j];
                    A[i][j] = sum;
                }
            }
            #pragma unroll
            for (int i = 0; i < 4; i++) {
                float s = bias[i*C_CH + ch];
                #pragma unroll
                for (int j = 0; j < 4; j++) s -= A[i][j] * m[j];
                d[i] = s;
            }

            float* __restrict__ P = &g_params[ch * 20];
            #pragma unroll
            for (int i = 0; i < 4; i++)
                #pragma unroll
                for (int j = 0; j < 4; j++)
                    P[i*4 + j] = A[i][j];
            #pragma unroll
            for (int i = 0; i < 4; i++) P[16 + i] = d[i];
        }
    }

    grid_barrier();

    // ---------------- Phase 3: apply (descending traversal) ----------------
    {
        // Reversed linear index: lin ascending -> group index descending.
        // g = total-1-lin; g mod 64 = 63 - (tid & 63)  (stride, 256 are mult of 64)
        const int c_ap = (C_CH - 1) - c;
        float P[20];
        #pragma unroll
        for (int k = 0; k < 20; k++) P[k] = g_params[c_ap * 20 + k];

        const float4* __restrict__ x4 = (const float4*)x;
        float4* __restrict__ o4 = (float4*)out;
        const long last = total_groups - 1;

        long lin = (long)blockIdx.x * NTHREADS + tid;
        for (; lin + 3*stride < total_groups; lin += 4*stride) {
            const long ga = last - lin;
            const long gb = last - (lin +   stride);
            const long gc = last - (lin + 2*stride);
            const long gd = last - (lin + 3*stride);
            float4 va = x4[ga];
            float4 vb = x4[gb];
            float4 vc = x4[gc];
            float4 vd = x4[gd];
            __stcs(&o4[ga], affine4(P, va));
            __stcs(&o4[gb], affine4(P, vb));
            __stcs(&o4[gc], affine4(P, vc));
            __stcs(&o4[gd], affine4(P, vd));
        }
        for (; lin < total_groups; lin += stride) {
            const long g = last - lin;
            float4 v = x4[g];
            __stcs(&o4[g], affine4(P, v));
        }
    }
}

// ---------------------------------------------------------------------------
extern "C" void kernel_launch(void* const* d_in, const int* in_sizes, int n_in,
                              void* d_out, int out_size) {
    const float* x      = (const float*)d_in[0];   // (B,H,W,C,I) fp32
    const float* weight = (const float*)d_in[1];   // (I,I,C)
    const float* bias   = (const float*)d_in[2];   // (I,C)
    float* out = (float*)d_out;

    const long total_elems  = (long)in_sizes[0];
    const long total_groups = total_elems / 4;              // float4 vectors
    const float n_count     = (float)(total_groups / C_CH); // B*H*W per channel

    fused_kernel<<<NBLOCKS, NTHREADS>>>(x, weight, bias, out, total_groups, n_count);
}